// round 5
// baseline (speedup 1.0000x reference)
#include <cuda_runtime.h>
#include <math.h>

#define NLEVELS 16
#define TSIZE (1u << 19)
#define TMASK (TSIZE - 1u)
#define HIDDEN 64
#define INDIM 32
#define OUTDIM 16
#define P2 2654435761u
#define P3 805459861u
#define TPB 256
#define NDENSE 5

__constant__ __align__(16) float cW0[HIDDEN * INDIM];   // [j][k]
__constant__ __align__(16) float cW1T[HIDDEN * OUTDIM]; // [j][o] (transposed host-side)
__constant__ float cB0[HIDDEN];
__constant__ float cB1[OUTDIM];

__device__ __constant__ const unsigned kRES[NDENSE] = {16u, 23u, 31u, 43u, 59u};

struct Params {
    float scale[NLEVELS];
};

typedef unsigned long long u64;

__device__ __forceinline__ u64 pk2(float lo, float hi) {
    u64 r;
    asm("mov.b64 %0, {%1, %2};" : "=l"(r) : "f"(lo), "f"(hi));
    return r;
}
__device__ __forceinline__ void upk2(float& lo, float& hi, u64 v) {
    asm("mov.b64 {%0, %1}, %2;" : "=f"(lo), "=f"(hi) : "l"(v));
}
__device__ __forceinline__ u64 fma2(u64 a, u64 b, u64 c) {
    u64 r;
    asm("fma.rn.f32x2 %0, %1, %2, %3;" : "=l"(r) : "l"(a), "l"(b), "l"(c));
    return r;
}

// Predicated vector load: r = cond ? *addr : fb, with NO branch (single @p LDG).
__device__ __forceinline__ float2 cond_ldg_f2(const float2* addr, unsigned cond, float2 fb) {
    float2 r = fb;
    asm("{\n\t"
        ".reg .pred p;\n\t"
        "setp.ne.u32 p, %2, 0;\n\t"
        "@p ld.global.nc.v2.f32 {%0,%1}, [%3];\n\t"
        "}"
        : "+f"(r.x), "+f"(r.y)
        : "r"(cond), "l"(addr));
    return r;
}

__global__ __launch_bounds__(TPB, 4) void sdf_fused_kernel(
    const float* __restrict__ x,
    const float* __restrict__ table,
    float* __restrict__ out,
    int N, Params p)
{
    __shared__ float sGeo[TPB * 15];

    int tid = threadIdx.x;
    int iBase = blockIdx.x * TPB;
    int i = iBase + tid;
    bool valid = (i < N);
    int ii = valid ? i : 0;

    float x0 = x[3 * ii + 0];
    float x1 = x[3 * ii + 1];
    float x2 = x[3 * ii + 2];
    float ux = fminf(fmaxf((x0 + 1.0f) * 0.5f, 0.0f), 1.0f);
    float uy = fminf(fmaxf((x1 + 1.0f) * 0.5f, 0.0f), 1.0f);
    float uz = fminf(fmaxf((x2 + 1.0f) * 0.5f, 0.0f), 1.0f);

    u64 enc2[NLEVELS];  // packed (feat0, feat1) per level
    const float2* __restrict__ tab = (const float2*)table;

#pragma unroll
    for (int l = 0; l < NLEVELS; l++) {
        float s = p.scale[l];
        float px = fmaf(ux, s, 0.5f);
        float py = fmaf(uy, s, 0.5f);
        float pz = fmaf(uz, s, 0.5f);
        float gx = floorf(px), gy = floorf(py), gz = floorf(pz);
        float fx = px - gx, fy = py - gy, fz = pz - gz;
        unsigned cx = (unsigned)gx, cy = (unsigned)gy, cz = (unsigned)gz;

        const float2* __restrict__ tl = tab + (size_t)l * TSIZE;
        const float4* __restrict__ tl4 = (const float4*)tl;

        float wx0 = 1.0f - fx;
        float wy0 = 1.0f - fy, wz0 = 1.0f - fz;
        float a0 = 0.0f, a1 = 0.0f;

        unsigned ty0, ty1, tz0, tz1;
        if (l < NDENSE) {
            unsigned r = kRES[l], r2 = r * r;
            ty0 = cy * r;  ty1 = ty0 + r;
            tz0 = cz * r2; tz1 = tz0 + r2;
        } else {
            ty0 = cy * P2; ty1 = ty0 + P2;
            tz0 = cz * P3; tz1 = tz0 + P3;
        }

#pragma unroll
        for (int c = 0; c < 4; c++) {
            unsigned oy = c & 1u, oz = (c >> 1) & 1u;
            unsigned tyz = (oy ? ty1 : ty0);
            unsigned tzz = (oz ? tz1 : tz0);
            unsigned jlo, jhi;
            if (l < NDENSE) {
                unsigned b = cx + tyz + tzz;
                jlo = b;
                jhi = b + 1u;
            } else {
                unsigned H = tyz ^ tzz;
                jlo = (cx ^ H) & TMASK;
                jhi = ((cx + 1u) ^ H) & TMASK;
            }
            float4 v = __ldg(tl4 + (jlo >> 1));
            unsigned odd = jlo & 1u;
            float2 flo = odd ? make_float2(v.z, v.w) : make_float2(v.x, v.y);
            float2 oth = odd ? make_float2(v.x, v.y) : make_float2(v.z, v.w);
            unsigned notpair = ((jlo ^ jhi) != 1u) ? 1u : 0u;
            float2 fhi = cond_ldg_f2(tl + jhi, notpair, oth);

            float wyz = (oy ? fy : wy0) * (oz ? fz : wz0);
            a0 = fmaf(fmaf(fhi.x, fx, flo.x * wx0), wyz, a0);
            a1 = fmaf(fmaf(fhi.y, fx, flo.y * wx0), wyz, a1);
        }
        enc2[l] = pk2(a0, a1);
    }

    // ---- MLP with packed f32x2 FMA; weights from constant (LDCU path) ----
    const u64* __restrict__ w0q = (const u64*)cW0;   // [j][16] pairs
    const u64* __restrict__ w1q = (const u64*)cW1T;  // [j][8]  pairs

    u64 acc2[OUTDIM / 2];
#pragma unroll
    for (int o2 = 0; o2 < OUTDIM / 2; o2++)
        acc2[o2] = pk2(cB1[2 * o2], cB1[2 * o2 + 1]);

#pragma unroll 8
    for (int j = 0; j < HIDDEN; j++) {
        u64 h2 = pk2(cB0[j], 0.0f);
#pragma unroll
        for (int k2 = 0; k2 < NLEVELS; k2++)
            h2 = fma2(enc2[k2], w0q[j * NLEVELS + k2], h2);
        float hlo, hhi;
        upk2(hlo, hhi, h2);
        float h = hlo + hhi;

        float z = 100.0f * h;
        float sp = __logf(1.0f + __expf(z)) * 0.01f;
        float a = (z > 20.0f) ? h : sp;

        u64 a2 = pk2(a, a);
#pragma unroll
        for (int o2 = 0; o2 < OUTDIM / 2; o2++)
            acc2[o2] = fma2(a2, w1q[j * (OUTDIM / 2) + o2], acc2[o2]);
    }

    float acc[OUTDIM];
#pragma unroll
    for (int o2 = 0; o2 < OUTDIM / 2; o2++)
        upk2(acc[2 * o2], acc[2 * o2 + 1], acc2[o2]);

    // ---- outputs: [sdf(N)] then [geo(N,15)], geo staged for coalescing ----
#pragma unroll
    for (int o = 0; o < 15; o++) sGeo[tid * 15 + o] = acc[o + 1];
    if (valid) out[i] = acc[0];
    __syncthreads();

    float* __restrict__ geo = out + N;
    size_t gbase = (size_t)iBase * 15;
    int total = (N - iBase) * 15;
    if (total > TPB * 15) total = TPB * 15;
    for (int t = tid; t < total; t += TPB)
        geo[gbase + t] = sGeo[t];
}

extern "C" void kernel_launch(void* const* d_in, const int* in_sizes, int n_in,
                              void* d_out, int out_size)
{
    const float* x     = (const float*)d_in[0];
    const float* table = (const float*)d_in[1];
    const float* W0    = (const float*)d_in[2];
    const float* b0    = (const float*)d_in[3];
    const float* W1    = (const float*)d_in[4];
    const float* b1    = (const float*)d_in[5];
    float* out = (float*)d_out;

    int N = in_sizes[0] / 3;

    cudaMemcpyToSymbolAsync(cW0, W0, HIDDEN * INDIM * sizeof(float), 0,
                            cudaMemcpyDeviceToDevice, 0);
    cudaMemcpyToSymbolAsync(cB0, b0, HIDDEN * sizeof(float), 0,
                            cudaMemcpyDeviceToDevice, 0);
    cudaMemcpyToSymbolAsync(cB1, b1, OUTDIM * sizeof(float), 0,
                            cudaMemcpyDeviceToDevice, 0);

    // Transpose W1 [16][64] -> cW1T [64][16] with 16 strided D2D copies.
    void* w1t_ptr = nullptr;
    cudaGetSymbolAddress(&w1t_ptr, cW1T);
    for (int o = 0; o < OUTDIM; o++) {
        // dst: cW1T[j*16 + o] (pitch 16 floats); src: W1[o*64 + j] (pitch 1 float)
        cudaMemcpy2DAsync((char*)w1t_ptr + o * sizeof(float), OUTDIM * sizeof(float),
                          W1 + o * HIDDEN, sizeof(float),
                          sizeof(float), HIDDEN,
                          cudaMemcpyDeviceToDevice, 0);
    }

    Params p;
    const double pls = exp2(7.0 / 15.0);
    for (int l = 0; l < NLEVELS; l++) {
        double sc = 16.0 * pow(pls, (double)l) - 1.0;
        p.scale[l] = (float)sc;
    }

    int blocks = (N + TPB - 1) / TPB;
    sdf_fused_kernel<<<blocks, TPB>>>(x, table, out, N, p);
}

// round 6
// speedup vs baseline: 1.1734x; 1.1734x over previous
#include <cuda_runtime.h>
#include <math.h>

#define NLEVELS 16
#define TSIZE (1u << 19)
#define TMASK (TSIZE - 1u)
#define HIDDEN 64
#define INDIM 32
#define OUTDIM 16
#define P2 2654435761u
#define P3 805459861u
#define TPB 256
#define NDENSE 5

__constant__ __align__(16) float cW0[HIDDEN * INDIM];   // [j][k]
__constant__ __align__(16) float cW1T[HIDDEN * OUTDIM]; // [j][o] (transposed host-side)
__constant__ float cB0[HIDDEN];
__constant__ float cB1[OUTDIM];

__device__ __constant__ const unsigned kRES[NDENSE] = {16u, 23u, 31u, 43u, 59u};

struct Params {
    float scale[NLEVELS];
};

typedef unsigned long long u64;

__device__ __forceinline__ u64 pk2(float lo, float hi) {
    u64 r;
    asm("mov.b64 %0, {%1, %2};" : "=l"(r) : "f"(lo), "f"(hi));
    return r;
}
__device__ __forceinline__ void upk2(float& lo, float& hi, u64 v) {
    asm("mov.b64 {%0, %1}, %2;" : "=f"(lo), "=f"(hi) : "l"(v));
}
__device__ __forceinline__ u64 fma2(u64 a, u64 b, u64 c) {
    u64 r;
    asm("fma.rn.f32x2 %0, %1, %2, %3;" : "=l"(r) : "l"(a), "l"(b), "l"(c));
    return r;
}

// Predicated load into an INDEPENDENT register pair (no dependency on other
// loads): issues as soon as the address/predicate are ready.
__device__ __forceinline__ float2 cond_ldg_f2_indep(const float2* addr, unsigned cond) {
    float2 r;
    asm("{\n\t"
        ".reg .pred p;\n\t"
        "setp.ne.u32 p, %2, 0;\n\t"
        "mov.f32 %0, 0f00000000;\n\t"
        "mov.f32 %1, 0f00000000;\n\t"
        "@p ld.global.nc.v2.f32 {%0,%1}, [%3];\n\t"
        "}"
        : "=f"(r.x), "=f"(r.y)
        : "r"(cond), "l"(addr));
    return r;
}

__global__ __launch_bounds__(TPB, 4) void sdf_fused_kernel(
    const float* __restrict__ x,
    const float* __restrict__ table,
    float* __restrict__ out,
    int N, Params p)
{
    __shared__ float sGeo[TPB * 15];

    int tid = threadIdx.x;
    int iBase = blockIdx.x * TPB;
    int i = iBase + tid;
    bool valid = (i < N);
    int ii = valid ? i : 0;

    float x0 = x[3 * ii + 0];
    float x1 = x[3 * ii + 1];
    float x2 = x[3 * ii + 2];
    float ux = fminf(fmaxf((x0 + 1.0f) * 0.5f, 0.0f), 1.0f);
    float uy = fminf(fmaxf((x1 + 1.0f) * 0.5f, 0.0f), 1.0f);
    float uz = fminf(fmaxf((x2 + 1.0f) * 0.5f, 0.0f), 1.0f);

    u64 enc2[NLEVELS];  // packed (feat0, feat1) per level
    const float2* __restrict__ tab = (const float2*)table;

#pragma unroll
    for (int l = 0; l < NLEVELS; l++) {
        float s = p.scale[l];
        float px = fmaf(ux, s, 0.5f);
        float py = fmaf(uy, s, 0.5f);
        float pz = fmaf(uz, s, 0.5f);
        float gx = floorf(px), gy = floorf(py), gz = floorf(pz);
        float fx = px - gx, fy = py - gy, fz = pz - gz;
        unsigned cx = (unsigned)gx, cy = (unsigned)gy, cz = (unsigned)gz;

        const float2* __restrict__ tl = tab + (size_t)l * TSIZE;
        const float4* __restrict__ tl4 = (const float4*)tl;

        float wx0 = 1.0f - fx;
        float wy0 = 1.0f - fy, wz0 = 1.0f - fz;
        float a0 = 0.0f, a1 = 0.0f;

        unsigned ty0, ty1, tz0, tz1;
        if (l < NDENSE) {
            unsigned r = kRES[l], r2 = r * r;
            ty0 = cy * r;  ty1 = ty0 + r;
            tz0 = cz * r2; tz1 = tz0 + r2;
        } else {
            ty0 = cy * P2; ty1 = ty0 + P2;
            tz0 = cz * P3; tz1 = tz0 + P3;
        }

        // --- phase 1: compute all indices, launch all loads (independent) ---
        float4 v[4];
        float2 t2[4];
        unsigned jloA[4], notpairA[4];
#pragma unroll
        for (int c = 0; c < 4; c++) {
            unsigned oy = c & 1u, oz = (c >> 1) & 1u;
            unsigned tyz = (oy ? ty1 : ty0);
            unsigned tzz = (oz ? tz1 : tz0);
            unsigned jlo, jhi;
            if (l < NDENSE) {
                unsigned b = cx + tyz + tzz;
                jlo = b;
                jhi = b + 1u;
            } else {
                unsigned H = tyz ^ tzz;
                jlo = (cx ^ H) & TMASK;
                jhi = ((cx + 1u) ^ H) & TMASK;
            }
            jloA[c] = jlo;
            notpairA[c] = ((jlo ^ jhi) != 1u) ? 1u : 0u;
            v[c] = __ldg(tl4 + (jlo >> 1));
            t2[c] = cond_ldg_f2_indep(tl + jhi, notpairA[c]);
        }
        // --- phase 2: select + interpolate ---
#pragma unroll
        for (int c = 0; c < 4; c++) {
            unsigned oy = c & 1u, oz = (c >> 1) & 1u;
            unsigned odd = jloA[c] & 1u;
            float2 flo = odd ? make_float2(v[c].z, v[c].w) : make_float2(v[c].x, v[c].y);
            float2 oth = odd ? make_float2(v[c].x, v[c].y) : make_float2(v[c].z, v[c].w);
            float2 fhi = notpairA[c] ? t2[c] : oth;

            float wyz = (oy ? fy : wy0) * (oz ? fz : wz0);
            a0 = fmaf(fmaf(fhi.x, fx, flo.x * wx0), wyz, a0);
            a1 = fmaf(fmaf(fhi.y, fx, flo.y * wx0), wyz, a1);
        }
        enc2[l] = pk2(a0, a1);
    }

    // ---- MLP with packed f32x2 FMA; weights from constant (uniform port) ----
    const u64* __restrict__ w0q = (const u64*)cW0;   // [j][16] pairs
    const u64* __restrict__ w1q = (const u64*)cW1T;  // [j][8]  pairs

    u64 acc2[OUTDIM / 2];
#pragma unroll
    for (int o2 = 0; o2 < OUTDIM / 2; o2++)
        acc2[o2] = pk2(cB1[2 * o2], cB1[2 * o2 + 1]);

#pragma unroll 8
    for (int j = 0; j < HIDDEN; j++) {
        u64 h2 = pk2(cB0[j], 0.0f);
#pragma unroll
        for (int k2 = 0; k2 < NLEVELS; k2++)
            h2 = fma2(enc2[k2], w0q[j * NLEVELS + k2], h2);
        float hlo, hhi;
        upk2(hlo, hhi, h2);
        float h = hlo + hhi;

        float z = 100.0f * h;
        float sp = __logf(1.0f + __expf(z)) * 0.01f;
        float a = (z > 20.0f) ? h : sp;

        u64 a2 = pk2(a, a);
#pragma unroll
        for (int o2 = 0; o2 < OUTDIM / 2; o2++)
            acc2[o2] = fma2(a2, w1q[j * (OUTDIM / 2) + o2], acc2[o2]);
    }

    float acc[OUTDIM];
#pragma unroll
    for (int o2 = 0; o2 < OUTDIM / 2; o2++)
        upk2(acc[2 * o2], acc[2 * o2 + 1], acc2[o2]);

    // ---- outputs: [sdf(N)] then [geo(N,15)], geo staged for coalescing ----
#pragma unroll
    for (int o = 0; o < 15; o++) sGeo[tid * 15 + o] = acc[o + 1];
    if (valid) out[i] = acc[0];
    __syncthreads();

    float* __restrict__ geo = out + N;
    size_t gbase = (size_t)iBase * 15;
    int total = (N - iBase) * 15;
    if (total > TPB * 15) total = TPB * 15;
    for (int t = tid; t < total; t += TPB)
        geo[gbase + t] = sGeo[t];
}

extern "C" void kernel_launch(void* const* d_in, const int* in_sizes, int n_in,
                              void* d_out, int out_size)
{
    const float* x     = (const float*)d_in[0];
    const float* table = (const float*)d_in[1];
    const float* W0    = (const float*)d_in[2];
    const float* b0    = (const float*)d_in[3];
    const float* W1    = (const float*)d_in[4];
    const float* b1    = (const float*)d_in[5];
    float* out = (float*)d_out;

    int N = in_sizes[0] / 3;

    cudaMemcpyToSymbolAsync(cW0, W0, HIDDEN * INDIM * sizeof(float), 0,
                            cudaMemcpyDeviceToDevice, 0);
    cudaMemcpyToSymbolAsync(cB0, b0, HIDDEN * sizeof(float), 0,
                            cudaMemcpyDeviceToDevice, 0);
    cudaMemcpyToSymbolAsync(cB1, b1, OUTDIM * sizeof(float), 0,
                            cudaMemcpyDeviceToDevice, 0);

    // Transpose W1 [16][64] -> cW1T [64][16] with 16 strided D2D copies.
    void* w1t_ptr = nullptr;
    cudaGetSymbolAddress(&w1t_ptr, cW1T);
    for (int o = 0; o < OUTDIM; o++) {
        cudaMemcpy2DAsync((char*)w1t_ptr + o * sizeof(float), OUTDIM * sizeof(float),
                          W1 + o * HIDDEN, sizeof(float),
                          sizeof(float), HIDDEN,
                          cudaMemcpyDeviceToDevice, 0);
    }

    Params p;
    const double pls = exp2(7.0 / 15.0);
    for (int l = 0; l < NLEVELS; l++) {
        double sc = 16.0 * pow(pls, (double)l) - 1.0;
        p.scale[l] = (float)sc;
    }

    int blocks = (N + TPB - 1) / TPB;
    sdf_fused_kernel<<<blocks, TPB>>>(x, table, out, N, p);
}

// round 7
// speedup vs baseline: 1.3014x; 1.1091x over previous
#include <cuda_runtime.h>
#include <math.h>

#define NLEVELS 16
#define TSIZE (1u << 19)
#define TMASK (TSIZE - 1u)
#define HIDDEN 64
#define INDIM 32
#define OUTDIM 16
#define P2 2654435761u
#define P3 805459861u
#define TPB 256
#define NDENSE 5

// dense level sizes: 16^3, 23^3, 31^3, 43^3, 59^3
#define DSZ0 4096
#define DSZ1 12167
#define DSZ2 29791
#define DSZ3 79507
#define DSZ4 205379
#define DOFF0 0
#define DOFF1 (DOFF0 + DSZ0)
#define DOFF2 (DOFF1 + DSZ1)
#define DOFF3 (DOFF2 + DSZ2)
#define DOFF4 (DOFF3 + DSZ3)
#define DTOT  (DOFF4 + DSZ4)   // 330940

__device__ float4 gDense[DTOT];

__constant__ __align__(16) float cW0[HIDDEN * INDIM];   // [j][k]
__constant__ __align__(16) float cW1T[HIDDEN * OUTDIM]; // [j][o]
__constant__ float cB0[HIDDEN];
__constant__ float cB1[OUTDIM];

struct Params {
    float scale[NLEVELS];
};

typedef unsigned long long u64;

__device__ __forceinline__ u64 pk2(float lo, float hi) {
    u64 r;
    asm("mov.b64 %0, {%1, %2};" : "=l"(r) : "f"(lo), "f"(hi));
    return r;
}
__device__ __forceinline__ void upk2(float& lo, float& hi, u64 v) {
    asm("mov.b64 {%0, %1}, %2;" : "=f"(lo), "=f"(hi) : "l"(v));
}
__device__ __forceinline__ u64 fma2(u64 a, u64 b, u64 c) {
    u64 r;
    asm("fma.rn.f32x2 %0, %1, %2, %3;" : "=l"(r) : "l"(a), "l"(b), "l"(c));
    return r;
}
__device__ __forceinline__ u64 mul2(u64 a, u64 b) {
    u64 r;
    asm("mul.rn.f32x2 %0, %1, %2;" : "=l"(r) : "l"(a), "l"(b));
    return r;
}

// Predicated load into INDEPENDENT registers (issues immediately).
__device__ __forceinline__ float2 cond_ldg_f2_indep(const float2* addr, unsigned cond) {
    float2 r;
    asm("{\n\t"
        ".reg .pred p;\n\t"
        "setp.ne.u32 p, %2, 0;\n\t"
        "mov.f32 %0, 0f00000000;\n\t"
        "mov.f32 %1, 0f00000000;\n\t"
        "@p ld.global.nc.v2.f32 {%0,%1}, [%3];\n\t"
        "}"
        : "=f"(r.x), "=f"(r.y)
        : "r"(cond), "l"(addr));
    return r;
}

// Build duplicated dense tables: gDense[off_l + b] = (tab_l[b], tab_l[b+1])
__global__ void build_dense_kernel(const float* __restrict__ table) {
    int t = blockIdx.x * blockDim.x + threadIdx.x;
    if (t >= DTOT) return;
    int l, off;
    if      (t < DOFF1) { l = 0; off = DOFF0; }
    else if (t < DOFF2) { l = 1; off = DOFF1; }
    else if (t < DOFF3) { l = 2; off = DOFF2; }
    else if (t < DOFF4) { l = 3; off = DOFF3; }
    else                { l = 4; off = DOFF4; }
    unsigned j = t - off;
    const float2* tl = (const float2*)table + (size_t)l * TSIZE;
    float2 a = tl[j];
    float2 b = tl[j + 1];   // j+1 <= res^3 <= T-1 region: always valid memory
    gDense[t] = make_float4(a.x, a.y, b.x, b.y);
}

__global__ __launch_bounds__(TPB, 4) void sdf_fused_kernel(
    const float* __restrict__ x,
    const float* __restrict__ table,
    float* __restrict__ out,
    int N, Params p)
{
    __shared__ float sGeo[TPB * 15];

    int tid = threadIdx.x;
    int iBase = blockIdx.x * TPB;
    int i = iBase + tid;
    bool valid = (i < N);
    int ii = valid ? i : 0;

    float x0 = x[3 * ii + 0];
    float x1 = x[3 * ii + 1];
    float x2 = x[3 * ii + 2];
    float ux = fminf(fmaxf((x0 + 1.0f) * 0.5f, 0.0f), 1.0f);
    float uy = fminf(fmaxf((x1 + 1.0f) * 0.5f, 0.0f), 1.0f);
    float uz = fminf(fmaxf((x2 + 1.0f) * 0.5f, 0.0f), 1.0f);

    u64 enc2[NLEVELS];  // packed (feat0, feat1) per level
    const float2* __restrict__ tab = (const float2*)table;

    const unsigned kRES[NDENSE] = {16u, 23u, 31u, 43u, 59u};
    const unsigned kOFF[NDENSE] = {DOFF0, DOFF1, DOFF2, DOFF3, DOFF4};

#pragma unroll
    for (int l = 0; l < NLEVELS; l++) {
        float s = p.scale[l];
        float px = fmaf(ux, s, 0.5f);
        float py = fmaf(uy, s, 0.5f);
        float pz = fmaf(uz, s, 0.5f);
        float gx = floorf(px), gy = floorf(py), gz = floorf(pz);
        float fx = px - gx, fy = py - gy, fz = pz - gz;
        unsigned cx = (unsigned)gx, cy = (unsigned)gy, cz = (unsigned)gz;

        float wx0 = 1.0f - fx;
        float wy0 = 1.0f - fy, wz0 = 1.0f - fz;
        u64 fx2 = pk2(fx, fx);
        u64 wx02 = pk2(wx0, wx0);
        u64 acc = pk2(0.0f, 0.0f);

        float wyzA[4];
        wyzA[0] = wy0 * wz0;
        wyzA[1] = fy  * wz0;
        wyzA[2] = wy0 * fz;
        wyzA[3] = fy  * fz;

        if (l < NDENSE) {
            unsigned r = kRES[l], r2 = r * r;
            unsigned base = kOFF[l] + cx;
            unsigned b00 = base + cy * r + cz * r2;
            unsigned bA[4] = {b00, b00 + r, b00 + r2, b00 + r + r2};
            float4 v[4];
#pragma unroll
            for (int c = 0; c < 4; c++) v[c] = __ldg(&gDense[bA[c]]);
#pragma unroll
            for (int c = 0; c < 4; c++) {
                u64 flo2 = pk2(v[c].x, v[c].y);
                u64 fhi2 = pk2(v[c].z, v[c].w);
                u64 t = mul2(flo2, wx02);
                t = fma2(fhi2, fx2, t);
                acc = fma2(t, pk2(wyzA[c], wyzA[c]), acc);
            }
        } else {
            const float2* __restrict__ tl = tab + (size_t)l * TSIZE;
            const float4* __restrict__ tl4 = (const float4*)tl;
            unsigned ty0 = cy * P2, ty1 = ty0 + P2;
            unsigned tz0 = cz * P3, tz1 = tz0 + P3;
            unsigned cxp1 = cx + 1u;

            float4 v[4];
            float2 t2[4];
            unsigned jloA[4], notpairA[4];
#pragma unroll
            for (int c = 0; c < 4; c++) {
                unsigned H = ((c & 1u) ? ty1 : ty0) ^ ((c & 2u) ? tz1 : tz0);
                unsigned jlo = (cx ^ H) & TMASK;
                unsigned jhi = (cxp1 ^ H) & TMASK;
                jloA[c] = jlo;
                notpairA[c] = ((jlo ^ jhi) != 1u) ? 1u : 0u;
                v[c] = __ldg(tl4 + (jlo >> 1));
                t2[c] = cond_ldg_f2_indep(tl + jhi, notpairA[c]);
            }
#pragma unroll
            for (int c = 0; c < 4; c++) {
                unsigned odd = jloA[c] & 1u;
                float2 flo = odd ? make_float2(v[c].z, v[c].w) : make_float2(v[c].x, v[c].y);
                float2 oth = odd ? make_float2(v[c].x, v[c].y) : make_float2(v[c].z, v[c].w);
                float2 fhi = notpairA[c] ? t2[c] : oth;
                u64 flo2 = pk2(flo.x, flo.y);
                u64 fhi2 = pk2(fhi.x, fhi.y);
                u64 t = mul2(flo2, wx02);
                t = fma2(fhi2, fx2, t);
                acc = fma2(t, pk2(wyzA[c], wyzA[c]), acc);
            }
        }
        enc2[l] = acc;
    }

    // ---- MLP with packed f32x2 FMA; weights from constant (uniform port) ----
    const u64* __restrict__ w0q = (const u64*)cW0;   // [j][16] pairs
    const u64* __restrict__ w1q = (const u64*)cW1T;  // [j][8]  pairs

    u64 acc2[OUTDIM / 2];
#pragma unroll
    for (int o2 = 0; o2 < OUTDIM / 2; o2++)
        acc2[o2] = pk2(cB1[2 * o2], cB1[2 * o2 + 1]);

#pragma unroll 8
    for (int j = 0; j < HIDDEN; j++) {
        u64 h2 = pk2(cB0[j], 0.0f);
#pragma unroll
        for (int k2 = 0; k2 < NLEVELS; k2++)
            h2 = fma2(enc2[k2], w0q[j * NLEVELS + k2], h2);
        float hlo, hhi;
        upk2(hlo, hhi, h2);
        float h = hlo + hhi;

        float z = 100.0f * h;
        float sp = __logf(1.0f + __expf(z)) * 0.01f;
        float a = (z > 20.0f) ? h : sp;

        u64 a2 = pk2(a, a);
#pragma unroll
        for (int o2 = 0; o2 < OUTDIM / 2; o2++)
            acc2[o2] = fma2(a2, w1q[j * (OUTDIM / 2) + o2], acc2[o2]);
    }

    float acc[OUTDIM];
#pragma unroll
    for (int o2 = 0; o2 < OUTDIM / 2; o2++)
        upk2(acc[2 * o2], acc[2 * o2 + 1], acc2[o2]);

    // ---- outputs: [sdf(N)] then [geo(N,15)], geo staged for coalescing ----
#pragma unroll
    for (int o = 0; o < 15; o++) sGeo[tid * 15 + o] = acc[o + 1];
    if (valid) out[i] = acc[0];
    __syncthreads();

    float* __restrict__ geo = out + N;
    size_t gbase = (size_t)iBase * 15;
    int total = (N - iBase) * 15;
    if (total > TPB * 15) total = TPB * 15;
    for (int t = tid; t < total; t += TPB)
        geo[gbase + t] = sGeo[t];
}

extern "C" void kernel_launch(void* const* d_in, const int* in_sizes, int n_in,
                              void* d_out, int out_size)
{
    const float* x     = (const float*)d_in[0];
    const float* table = (const float*)d_in[1];
    const float* W0    = (const float*)d_in[2];
    const float* b0    = (const float*)d_in[3];
    const float* W1    = (const float*)d_in[4];
    const float* b1    = (const float*)d_in[5];
    float* out = (float*)d_out;

    int N = in_sizes[0] / 3;

    cudaMemcpyToSymbolAsync(cW0, W0, HIDDEN * INDIM * sizeof(float), 0,
                            cudaMemcpyDeviceToDevice, 0);
    cudaMemcpyToSymbolAsync(cB0, b0, HIDDEN * sizeof(float), 0,
                            cudaMemcpyDeviceToDevice, 0);
    cudaMemcpyToSymbolAsync(cB1, b1, OUTDIM * sizeof(float), 0,
                            cudaMemcpyDeviceToDevice, 0);

    // Transpose W1 [16][64] -> cW1T [64][16] with 16 strided D2D copies.
    void* w1t_ptr = nullptr;
    cudaGetSymbolAddress(&w1t_ptr, cW1T);
    for (int o = 0; o < OUTDIM; o++) {
        cudaMemcpy2DAsync((char*)w1t_ptr + o * sizeof(float), OUTDIM * sizeof(float),
                          W1 + o * HIDDEN, sizeof(float),
                          sizeof(float), HIDDEN,
                          cudaMemcpyDeviceToDevice, 0);
    }

    // Build duplicated dense tables (graph-capturable kernel launch).
    build_dense_kernel<<<(DTOT + 255) / 256, 256>>>(table);

    Params p;
    const double pls = exp2(7.0 / 15.0);
    for (int l = 0; l < NLEVELS; l++) {
        double sc = 16.0 * pow(pls, (double)l) - 1.0;
        p.scale[l] = (float)sc;
    }

    int blocks = (N + TPB - 1) / TPB;
    sdf_fused_kernel<<<blocks, TPB>>>(x, table, out, N, p);
}